// round 9
// baseline (speedup 1.0000x reference)
#include <cuda_runtime.h>
#include <cstdint>

// RWKV7 chunked attention, B=4 T=2048 H=32 C=64 dT=16.
// One CTA (512 thr) per (b,h). Software pipeline:
//   producer warps 8-15: chunk ch+1 stage + grams + AKV/QKV + ACCV (state-independent)
//   consumer warps 0-7 : chunk ch   state GEMM + solve + y + state update
// R8: warp->tile mappings rearranged for 1-wavefront LDS (4x8 coverage), AKQK
// transposed [s][t] stride-36 to kill bank conflicts.

#define B_ 4
#define T_ 2048
#define H_ 32
#define C_ 64
#define DT_ 16
#define NT_ 128
#define THREADS 512

typedef unsigned long long u64;

// ---- shared layout (float words) ----
#define OFF_S    0          // [64][64] sg swizzle
#define OFF_U    4096       // [16][64] tg swizzle
#define OFF_ABU  5120       // [16][64]
#define OFF_AKQK 6144       // transposed: entry (s,t) at s*36 + t*2 (u64 pairs)
#define OFF_LPP  6720       // [4][64] producer prefix scratch
#define OFF_BUF  6976
#define BUF_STRIDE 7744
// offsets within one buffer:
#define BWA  0
#define BWQ  1024
#define BKWI 2048
#define BBWI 3072
#define BV   4096
#define BAKV 5120
#define BQKV 6144
#define BAB  7168
#define BQB  7424
#define BFW  7680
#define OFF_ACCV (OFF_BUF + 2 * BUF_STRIDE)      // 2 x [64][64] sg swizzle
#define SMEM_WORDS (OFF_ACCV + 2 * 4096)
#define SMEM_BYTES (SMEM_WORDS * 4)

#define BARC() asm volatile("bar.sync 1, 256;" ::: "memory")   // consumer group
#define BARP() asm volatile("bar.sync 2, 256;" ::: "memory")   // producer group

// xor swizzles
__device__ __forceinline__ int tg(int t, int f)  { return t * 64 + (((f ^ t) & 15) << 2); }
__device__ __forceinline__ int tw(int t, int c)  { return t * 64 + ((((c >> 2) ^ t) & 15) << 2) + (c & 3); }
__device__ __forceinline__ int sg(int r, int f)  { return r * 64 + (((f ^ (r >> 2)) & 15) << 2); }
__device__ __forceinline__ int akx(int s, int t) { return s * 36 + t * 2; }   // AKQK (s,t)

__device__ __forceinline__ float4 ld4(const float* p) { return *reinterpret_cast<const float4*>(p); }
__device__ __forceinline__ void st4(float* p, float4 v) { *reinterpret_cast<float4*>(p) = v; }
__device__ __forceinline__ ulonglong2 ldp(const float* p) { return *reinterpret_cast<const ulonglong2*>(p); }
__device__ __forceinline__ void stp(float* p, ulonglong2 v) { *reinterpret_cast<ulonglong2*>(p) = v; }

__device__ __forceinline__ u64 pk2(float lo, float hi) {
    u64 r; asm("mov.b64 %0, {%1, %2};" : "=l"(r) : "f"(lo), "f"(hi)); return r;
}
__device__ __forceinline__ void un2(u64 v, float& lo, float& hi) {
    asm("mov.b64 {%0, %1}, %2;" : "=f"(lo), "=f"(hi) : "l"(v));
}
__device__ __forceinline__ void fma2(u64& d, u64 a, u64 b) {
    asm("fma.rn.f32x2 %0, %1, %2, %0;" : "+l"(d) : "l"(a), "l"(b));
}
__device__ __forceinline__ u64 add2(u64 a, u64 b) {
    u64 d; asm("add.rn.f32x2 %0, %1, %2;" : "=l"(d) : "l"(a), "l"(b)); return d;
}
__device__ __forceinline__ u64 mul2(u64 a, u64 b) {
    u64 d; asm("mul.rn.f32x2 %0, %1, %2;" : "=l"(d) : "l"(a), "l"(b)); return d;
}

// ---------- producer: stage chunk cp into buffer buf, accv into av ----------
__device__ __forceinline__ void produce(
    float* __restrict__ sm, float* __restrict__ buf, float* __restrict__ av,
    const float* __restrict__ gw, const float* __restrict__ gq,
    const float* __restrict__ gk, const float* __restrict__ gv,
    const float* __restrict__ ga, const float* __restrict__ gb,
    int b, int h, int cp, int pt)
{
    const int th = pt >> 6;        // 0..3, owns t = 4*th + r
    const int cl = pt & 63;
    const size_t strT = (size_t)H_ * C_;
    // 4x8 warp mappings (row4 spans 16 via warp bits 0-1, col8 via warp bit 2)
    const int wmp  = pt >> 5;
    const int row4 = (wmp & 3) * 4 + ((pt >> 3) & 3);   // 0..15
    const int col8 = ((wmp >> 2) & 1) * 8 + (pt & 7);   // 0..15

    // load + decay + stage
    {
        size_t base = (((size_t)b * T_ + cp * DT_ + 4 * th) * H_ + h) * C_ + cl;
        float rw[4], rq[4], rk[4], rv[4], ra[4], rb[4];
        #pragma unroll
        for (int r = 0; r < 4; r++) {
            size_t ix = base + (size_t)r * strT;
            rw[r] = gw[ix]; rq[r] = gq[ix]; rk[r] = gk[ix];
            rv[r] = gv[ix]; ra[r] = ga[ix]; rb[r] = gb[ix];
        }
        float wd[4]; float lp = 1.f;
        #pragma unroll
        for (int r = 0; r < 4; r++) { wd[r] = __expf(-__expf(rw[r])); lp *= wd[r]; }
        sm[OFF_LPP + th * 64 + cl] = lp;
        BARP();
        float incl = 1.f;
        #pragma unroll
        for (int gg = 0; gg < 3; gg++)
            if (gg < th) incl *= sm[OFF_LPP + gg * 64 + cl];
        #pragma unroll
        for (int r = 0; r < 4; r++) {
            int t = 4 * th + r;
            float ip = incl; incl *= wd[r];
            float rinv = __fdividef(1.f, incl);
            int twd = tw(t, cl);
            buf[BWQ  + twd] = rq[r] * incl;
            buf[BWA  + twd] = ra[r] * ip;
            buf[BKWI + twd] = rk[r] * rinv;
            buf[BBWI + twd] = rb[r] * rinv;
            buf[BV   + twd] = rv[r];
        }
        if (th == 3) buf[BFW + cl] = incl;
    }
    BARP();

    // grams: thread (t = row4, s = col8)
    {
        const int t = row4, s = col8;
        u64 ab2 = 0, ak2 = 0, qb2 = 0, qk2 = 0;
        #pragma unroll
        for (int c4 = 0; c4 < 16; c4++) {
            ulonglong2 A  = ldp(buf + BWA  + tg(t, c4));
            ulonglong2 Q  = ldp(buf + BWQ  + tg(t, c4));
            ulonglong2 Bv = ldp(buf + BBWI + tg(s, c4));
            ulonglong2 Kv = ldp(buf + BKWI + tg(s, c4));
            fma2(ab2, A.x, Bv.x); fma2(ab2, A.y, Bv.y);
            fma2(ak2, A.x, Kv.x); fma2(ak2, A.y, Kv.y);
            fma2(qb2, Q.x, Bv.x); fma2(qb2, Q.y, Bv.y);
            fma2(qk2, Q.x, Kv.x); fma2(qk2, Q.y, Kv.y);
        }
        float l, hh, ab, ak, qb, qk;
        un2(ab2, l, hh); ab = l + hh;
        un2(ak2, l, hh); ak = l + hh;
        un2(qb2, l, hh); qb = l + hh;
        un2(qk2, l, hh); qk = l + hh;
        float ms = (t > s)  ? 1.f : 0.f;
        float mi = (t >= s) ? 1.f : 0.f;
        buf[BAB + t * 16 + s] = ab * ms;
        buf[BQB + t * 16 + s] = qb * mi;
        *reinterpret_cast<u64*>(sm + OFF_AKQK + akx(s, t)) = pk2(ak * ms, qk * mi);
    }
    BARP();

    // AKV = ak@v, QKV = qk@v : thread (t = row4, iq = col8)
    {
        const int t = row4, iq = col8;
        u64 acc[4] = {0, 0, 0, 0};
        #pragma unroll
        for (int s = 0; s < 16; s++) {
            u64 akqk = *reinterpret_cast<const u64*>(sm + OFF_AKQK + akx(s, t));
            float4 v4 = ld4(buf + BV + tg(s, iq));
            fma2(acc[0], akqk, pk2(v4.x, v4.x));
            fma2(acc[1], akqk, pk2(v4.y, v4.y));
            fma2(acc[2], akqk, pk2(v4.z, v4.z));
            fma2(acc[3], akqk, pk2(v4.w, v4.w));
        }
        float akv[4], qkv[4];
        #pragma unroll
        for (int r = 0; r < 4; r++) un2(acc[r], akv[r], qkv[r]);
        st4(buf + BAKV + tg(t, iq), make_float4(akv[0], akv[1], akv[2], akv[3]));
        st4(buf + BQKV + tg(t, iq), make_float4(qkv[0], qkv[1], qkv[2], qkv[3]));
    }

    // ACCV = v^T kwi -> av : thread (iq2 = row4, jq = col8)
    {
        const int iq2 = row4, jq = col8;
        u64 acc[4][2];
        #pragma unroll
        for (int r = 0; r < 4; r++) { acc[r][0] = 0; acc[r][1] = 0; }
        #pragma unroll
        for (int t = 0; t < DT_; t++) {
            float4 v4 = ld4(buf + BV + tg(t, iq2));
            ulonglong2 K2 = ldp(buf + BKWI + tg(t, jq));
            u64 v0 = pk2(v4.x, v4.x), v1 = pk2(v4.y, v4.y);
            u64 v2 = pk2(v4.z, v4.z), v3 = pk2(v4.w, v4.w);
            fma2(acc[0][0], v0, K2.x); fma2(acc[0][1], v0, K2.y);
            fma2(acc[1][0], v1, K2.x); fma2(acc[1][1], v1, K2.y);
            fma2(acc[2][0], v2, K2.x); fma2(acc[2][1], v2, K2.y);
            fma2(acc[3][0], v3, K2.x); fma2(acc[3][1], v3, K2.y);
        }
        #pragma unroll
        for (int r = 0; r < 4; r++) {
            ulonglong2 o; o.x = acc[r][0]; o.y = acc[r][1];
            stp(av + sg(4 * iq2 + r, jq), o);
        }
    }
}

__global__ __launch_bounds__(THREADS, 1)
void rwkv7_kernel(const float* __restrict__ gw, const float* __restrict__ gq,
                  const float* __restrict__ gk, const float* __restrict__ gv,
                  const float* __restrict__ ga, const float* __restrict__ gb,
                  const float* __restrict__ gs0, float* __restrict__ gy)
{
    extern __shared__ float sm[];

    const int bh  = blockIdx.x;
    const int b   = bh / H_;
    const int h   = bh % H_;
    const int tid = threadIdx.x;
    const bool is_prod = tid >= 256;
    const int pt = tid & 255;

    // consumer mappings: warp covers 4 rows x 8 cols
    const int w    = pt >> 5;
    const int tx   = (w & 3) * 4 + ((pt >> 3) & 3);      // GEMM/y: t
    const int iq   = ((w >> 2) & 1) * 8 + (pt & 7);      // GEMM/y: i-quad
    const int iq2  = tx;                                  // update: i-quad (4x8 map)
    const int jq   = iq;                                  // update: j-quad

    // ---- bootstrap ----
    if (is_prod) {
        produce(sm, sm + OFF_BUF, sm + OFF_ACCV, gw, gq, gk, gv, ga, gb, b, h, 0, pt);
    } else {
        const float* s0p = gs0 + (size_t)bh * 4096;
        #pragma unroll
        for (int q4 = pt; q4 < 1024; q4 += 256) {
            int row = q4 >> 4, f = q4 & 15;
            st4(sm + OFF_S + sg(row, f), ld4(s0p + row * 64 + f * 4));
        }
    }
    __syncthreads();

    for (int ch = 0; ch < NT_; ch++) {
        const int p = ch & 1;

        if (is_prod) {
            if (ch + 1 < NT_)
                produce(sm, sm + OFF_BUF + (p ^ 1) * BUF_STRIDE,
                        sm + OFF_ACCV + (p ^ 1) * 4096,
                        gw, gq, gk, gv, ga, gb, b, h, ch + 1, pt);
        } else {
            float* buf = sm + OFF_BUF + p * BUF_STRIDE;
            float* av  = sm + OFF_ACCV + p * 4096;

            // ===== state GEMM: aa = wa@S^T, ay = wq@S^T =====
            float yp[4];
            {
                u64 aa2[4] = {0,0,0,0}, ay2[4] = {0,0,0,0};
                #pragma unroll
                for (int j4 = 0; j4 < 16; j4++) {
                    ulonglong2 A = ldp(buf + BWA + tg(tx, j4));
                    ulonglong2 Q = ldp(buf + BWQ + tg(tx, j4));
                    #pragma unroll
                    for (int r = 0; r < 4; r++) {
                        ulonglong2 S = ldp(sm + OFF_S + sg(4 * iq + r, j4));
                        fma2(aa2[r], A.x, S.x); fma2(aa2[r], A.y, S.y);
                        fma2(ay2[r], Q.x, S.x); fma2(ay2[r], Q.y, S.y);
                    }
                }
                float4 akv4 = ld4(buf + BAKV + tg(tx, iq));
                float4 qkv4 = ld4(buf + BQKV + tg(tx, iq));
                float abu[4];
                float l0, h0, l1, h1;
                un2(aa2[0], l0, h0); un2(ay2[0], l1, h1);
                abu[0] = l0 + h0 + akv4.x; yp[0] = l1 + h1 + qkv4.x;
                un2(aa2[1], l0, h0); un2(ay2[1], l1, h1);
                abu[1] = l0 + h0 + akv4.y; yp[1] = l1 + h1 + qkv4.y;
                un2(aa2[2], l0, h0); un2(ay2[2], l1, h1);
                abu[2] = l0 + h0 + akv4.z; yp[2] = l1 + h1 + qkv4.z;
                un2(aa2[3], l0, h0); un2(ay2[3], l1, h1);
                abu[3] = l0 + h0 + akv4.w; yp[3] = l1 + h1 + qkv4.w;
                st4(sm + OFF_ABU + tg(tx, iq),
                    make_float4(abu[0], abu[1], abu[2], abu[3]));
            }
            BARC();   // abu complete

            // ===== solve (I-ab) u = abu (64 columns, 2 warps) =====
            if (pt < 64) {
                const int c = pt;
                float uu[DT_];
                #pragma unroll
                for (int t = 0; t < DT_; t++) uu[t] = sm[OFF_ABU + tw(t, c)];
                #pragma unroll
                for (int t = 1; t < DT_; t++) {
                    float a0 = uu[t], a1 = 0.f, a2 = 0.f, a3 = 0.f;
                    const float* abr = buf + BAB + t * 16;
                    #pragma unroll
                    for (int s4 = 0; 4 * s4 < t; s4++) {
                        float4 abq = ld4(abr + 4 * s4);
                        int s = 4 * s4;
                        if (s     < t) a0 += abq.x * uu[s];
                        if (s + 1 < t) a1 += abq.y * uu[s + 1];
                        if (s + 2 < t) a2 += abq.z * uu[s + 2];
                        if (s + 3 < t) a3 += abq.w * uu[s + 3];
                    }
                    uu[t] = (a0 + a1) + (a2 + a3);
                }
                #pragma unroll
                for (int t = 0; t < DT_; t++) sm[OFF_U + tw(t, c)] = uu[t];
            }
            BARC();   // u ready

            // ===== y = yp + qb@u =====
            {
                float4 qbr[4];
                #pragma unroll
                for (int r = 0; r < 4; r++) qbr[r] = ld4(buf + BQB + tx * 16 + 4 * r);
                u64 y01 = pk2(yp[0], yp[1]);
                u64 y23 = pk2(yp[2], yp[3]);
                #pragma unroll
                for (int s = 0; s < 16; s++) {
                    float qbs = (s & 2) ? ((s & 1) ? qbr[s >> 2].w : qbr[s >> 2].z)
                                        : ((s & 1) ? qbr[s >> 2].y : qbr[s >> 2].x);
                    ulonglong2 U2 = ldp(sm + OFF_U + tg(s, iq));
                    u64 q2 = pk2(qbs, qbs);
                    fma2(y01, q2, U2.x);
                    fma2(y23, q2, U2.y);
                }
                float o0, o1, o2, o3;
                un2(y01, o0, o1); un2(y23, o2, o3);
                size_t yb = (((size_t)b * T_ + ch * DT_ + tx) * H_ + h) * C_ + 4 * iq;
                __stcs(reinterpret_cast<float4*>(gy + yb), make_float4(o0, o1, o2, o3));
            }

            // ===== state update: S = (S + accv(from producer) + u^T bwi) * fw =====
            {
                u64 accR[4][2];
                #pragma unroll
                for (int r = 0; r < 4; r++) {
                    ulonglong2 A0 = ldp(av + sg(4 * iq2 + r, jq));
                    accR[r][0] = A0.x; accR[r][1] = A0.y;
                }
                #pragma unroll
                for (int t = 0; t < DT_; t++) {
                    float4 u4 = ld4(sm + OFF_U + tg(t, iq2));
                    ulonglong2 B2 = ldp(buf + BBWI + tg(t, jq));
                    u64 u0 = pk2(u4.x, u4.x), u1 = pk2(u4.y, u4.y);
                    u64 u2 = pk2(u4.z, u4.z), u3 = pk2(u4.w, u4.w);
                    fma2(accR[0][0], u0, B2.x); fma2(accR[0][1], u0, B2.y);
                    fma2(accR[1][0], u1, B2.x); fma2(accR[1][1], u1, B2.y);
                    fma2(accR[2][0], u2, B2.x); fma2(accR[2][1], u2, B2.y);
                    fma2(accR[3][0], u3, B2.x); fma2(accR[3][1], u3, B2.y);
                }
                ulonglong2 FWp = ldp(buf + BFW + 4 * jq);
                #pragma unroll
                for (int r = 0; r < 4; r++) {
                    float* sp = sm + OFF_S + sg(4 * iq2 + r, jq);
                    ulonglong2 S = ldp(sp);
                    S.x = mul2(add2(S.x, accR[r][0]), FWp.x);
                    S.y = mul2(add2(S.y, accR[r][1]), FWp.y);
                    stp(sp, S);
                }
            }
        }
        __syncthreads();   // buffer handoff
    }
}

extern "C" void kernel_launch(void* const* d_in, const int* in_sizes, int n_in,
                              void* d_out, int out_size)
{
    const float* w  = (const float*)d_in[0];
    const float* q  = (const float*)d_in[1];
    const float* k  = (const float*)d_in[2];
    const float* v  = (const float*)d_in[3];
    const float* a  = (const float*)d_in[4];
    const float* b  = (const float*)d_in[5];
    const float* s0 = (const float*)d_in[6];
    float* y = (float*)d_out;

    cudaFuncSetAttribute(rwkv7_kernel, cudaFuncAttributeMaxDynamicSharedMemorySize, SMEM_BYTES);
    rwkv7_kernel<<<B_ * H_, THREADS, SMEM_BYTES>>>(w, q, k, v, a, b, s0, y);
}

// round 11
// speedup vs baseline: 1.1713x; 1.1713x over previous
#include <cuda_runtime.h>
#include <cstdint>

// RWKV7 chunked attention, B=4 T=2048 H=32 C=64 dT=16.
// One CTA (512 thr) per (b,h). Producer/consumer pipeline; consumer state GEMM
// [wa;wq] @ S^T done with mma.sync m16n8k8 tf32 (plain-target HMMA).

#define B_ 4
#define T_ 2048
#define H_ 32
#define C_ 64
#define DT_ 16
#define NT_ 128
#define THREADS 512

typedef unsigned long long u64;

// ---- shared layout (float words) ----
#define OFF_S    0          // [64][68] plain
#define OFF_U    4352       // [16][64] tg swizzle
#define OFF_ABU  5376       // [16][68] plain (raw GEMM out, wa rows)
#define OFF_YP   6464       // [16][68] plain (raw GEMM out, wq rows)
#define OFF_AKQK 7552       // (s,t) u64 pairs stride 36
#define OFF_LPP  8128       // [4][64]
#define OFF_BUF  8384
// per-buffer offsets:
#define BWAQ 0              // [32][68] plain, tf32-rounded (rows 0-15 wa, 16-31 wq)
#define BKWI 2176           // [16][64] tg/tw swizzle
#define BBWI 3200
#define BV   4224
#define BAKV 5248           // [16][68] plain
#define BQKV 6336           // [16][68] plain
#define BAB  7424           // [16][16]
#define BQB  7680
#define BFW  7936           // [64]
#define BUF_STRIDE 8000
#define OFF_ACCV (OFF_BUF + 2 * BUF_STRIDE)   // 2 x [64][64] sg swizzle
#define SMEM_WORDS (OFF_ACCV + 2 * 4096)
#define SMEM_BYTES (SMEM_WORDS * 4)

#define BARC() asm volatile("bar.sync 1, 256;" ::: "memory")   // consumer group
#define BARP() asm volatile("bar.sync 2, 256;" ::: "memory")   // producer group

// xor swizzles for [16][64] tiles
__device__ __forceinline__ int tg(int t, int f)  { return t * 64 + (((f ^ t) & 15) << 2); }
__device__ __forceinline__ int tw(int t, int c)  { return t * 64 + ((((c >> 2) ^ t) & 15) << 2) + (c & 3); }
// accv tile [64][64] swizzle
__device__ __forceinline__ int sg(int r, int f)  { return r * 64 + (((f ^ (r >> 2)) & 15) << 2); }
__device__ __forceinline__ int akx(int s, int t) { return s * 36 + t * 2; }

__device__ __forceinline__ float4 ld4(const float* p) { return *reinterpret_cast<const float4*>(p); }
__device__ __forceinline__ void st4(float* p, float4 v) { *reinterpret_cast<float4*>(p) = v; }
__device__ __forceinline__ ulonglong2 ldp(const float* p) { return *reinterpret_cast<const ulonglong2*>(p); }
__device__ __forceinline__ void stp(float* p, ulonglong2 v) { *reinterpret_cast<ulonglong2*>(p) = v; }

__device__ __forceinline__ u64 pk2(float lo, float hi) {
    u64 r; asm("mov.b64 %0, {%1, %2};" : "=l"(r) : "f"(lo), "f"(hi)); return r;
}
__device__ __forceinline__ void un2(u64 v, float& lo, float& hi) {
    asm("mov.b64 {%0, %1}, %2;" : "=f"(lo), "=f"(hi) : "l"(v));
}
__device__ __forceinline__ void fma2(u64& d, u64 a, u64 b) {
    asm("fma.rn.f32x2 %0, %1, %2, %0;" : "+l"(d) : "l"(a), "l"(b));
}
__device__ __forceinline__ u64 add2(u64 a, u64 b) {
    u64 d; asm("add.rn.f32x2 %0, %1, %2;" : "=l"(d) : "l"(a), "l"(b)); return d;
}
__device__ __forceinline__ u64 mul2(u64 a, u64 b) {
    u64 d; asm("mul.rn.f32x2 %0, %1, %2;" : "=l"(d) : "l"(a), "l"(b)); return d;
}
__device__ __forceinline__ float tf32r(float x) {
    uint32_t r; asm("cvt.rna.tf32.f32 %0, %1;" : "=r"(r) : "f"(x));
    return __uint_as_float(r);
}
__device__ __forceinline__ void mma8(float4& d, uint32_t a0, uint32_t a1, uint32_t a2,
                                     uint32_t a3, uint32_t b0, uint32_t b1) {
    asm volatile(
        "mma.sync.aligned.m16n8k8.row.col.f32.tf32.tf32.f32 "
        "{%0,%1,%2,%3}, {%4,%5,%6,%7}, {%8,%9}, {%0,%1,%2,%3};"
        : "+f"(d.x), "+f"(d.y), "+f"(d.z), "+f"(d.w)
        : "r"(a0), "r"(a1), "r"(a2), "r"(a3), "r"(b0), "r"(b1));
}

// ---------- producer: stage chunk cp into buf, accv into av ----------
__device__ __forceinline__ void produce(
    float* __restrict__ sm, float* __restrict__ buf, float* __restrict__ av,
    const float* __restrict__ gw, const float* __restrict__ gq,
    const float* __restrict__ gk, const float* __restrict__ gv,
    const float* __restrict__ ga, const float* __restrict__ gb,
    int b, int h, int cp, int pt)
{
    const int th = pt >> 6;
    const int cl = pt & 63;
    const size_t strT = (size_t)H_ * C_;
    const int wmp  = pt >> 5;
    const int row4 = (wmp & 3) * 4 + ((pt >> 3) & 3);
    const int col8 = ((wmp >> 2) & 1) * 8 + (pt & 7);

    // load + decay + stage
    {
        size_t base = (((size_t)b * T_ + cp * DT_ + 4 * th) * H_ + h) * C_ + cl;
        float rw[4], rq[4], rk[4], rv[4], ra[4], rb[4];
        #pragma unroll
        for (int r = 0; r < 4; r++) {
            size_t ix = base + (size_t)r * strT;
            rw[r] = gw[ix]; rq[r] = gq[ix]; rk[r] = gk[ix];
            rv[r] = gv[ix]; ra[r] = ga[ix]; rb[r] = gb[ix];
        }
        float wd[4]; float lp = 1.f;
        #pragma unroll
        for (int r = 0; r < 4; r++) { wd[r] = __expf(-__expf(rw[r])); lp *= wd[r]; }
        sm[OFF_LPP + th * 64 + cl] = lp;
        BARP();
        float incl = 1.f;
        #pragma unroll
        for (int gg = 0; gg < 3; gg++)
            if (gg < th) incl *= sm[OFF_LPP + gg * 64 + cl];
        #pragma unroll
        for (int r = 0; r < 4; r++) {
            int t = 4 * th + r;
            float ip = incl; incl *= wd[r];
            float rinv = __fdividef(1.f, incl);
            int twd = tw(t, cl);
            buf[BWAQ + t * 68 + cl]        = tf32r(ra[r] * ip);     // wa row t
            buf[BWAQ + (16 + t) * 68 + cl] = tf32r(rq[r] * incl);   // wq row 16+t
            buf[BKWI + twd] = rk[r] * rinv;
            buf[BBWI + twd] = rb[r] * rinv;
            buf[BV   + twd] = rv[r];
        }
        if (th == 3) buf[BFW + cl] = incl;
    }
    BARP();

    // grams (reads tf32-rounded wa/wq; ~1e-4 perturbation, within budget)
    {
        const int t = row4, s = col8;
        u64 ab2 = 0, ak2 = 0, qb2 = 0, qk2 = 0;
        #pragma unroll
        for (int c4 = 0; c4 < 16; c4++) {
            ulonglong2 A  = ldp(buf + BWAQ + t * 68 + 4 * c4);
            ulonglong2 Q  = ldp(buf + BWAQ + (16 + t) * 68 + 4 * c4);
            ulonglong2 Bv = ldp(buf + BBWI + tg(s, c4));
            ulonglong2 Kv = ldp(buf + BKWI + tg(s, c4));
            fma2(ab2, A.x, Bv.x); fma2(ab2, A.y, Bv.y);
            fma2(ak2, A.x, Kv.x); fma2(ak2, A.y, Kv.y);
            fma2(qb2, Q.x, Bv.x); fma2(qb2, Q.y, Bv.y);
            fma2(qk2, Q.x, Kv.x); fma2(qk2, Q.y, Kv.y);
        }
        float l, hh, ab, ak, qb, qk;
        un2(ab2, l, hh); ab = l + hh;
        un2(ak2, l, hh); ak = l + hh;
        un2(qb2, l, hh); qb = l + hh;
        un2(qk2, l, hh); qk = l + hh;
        float ms = (t > s)  ? 1.f : 0.f;
        float mi = (t >= s) ? 1.f : 0.f;
        buf[BAB + t * 16 + s] = ab * ms;
        buf[BQB + t * 16 + s] = qb * mi;
        *reinterpret_cast<u64*>(sm + OFF_AKQK + akx(s, t)) = pk2(ak * ms, qk * mi);
    }
    BARP();

    // AKV = ak@v, QKV = qk@v -> plain [16][68]
    {
        const int t = row4, iq = col8;
        u64 acc[4] = {0, 0, 0, 0};
        #pragma unroll
        for (int s = 0; s < 16; s++) {
            u64 akqk = *reinterpret_cast<const u64*>(sm + OFF_AKQK + akx(s, t));
            float4 v4 = ld4(buf + BV + tg(s, iq));
            fma2(acc[0], akqk, pk2(v4.x, v4.x));
            fma2(acc[1], akqk, pk2(v4.y, v4.y));
            fma2(acc[2], akqk, pk2(v4.z, v4.z));
            fma2(acc[3], akqk, pk2(v4.w, v4.w));
        }
        float akv[4], qkv[4];
        #pragma unroll
        for (int r = 0; r < 4; r++) un2(acc[r], akv[r], qkv[r]);
        st4(buf + BAKV + t * 68 + 4 * iq, make_float4(akv[0], akv[1], akv[2], akv[3]));
        st4(buf + BQKV + t * 68 + 4 * iq, make_float4(qkv[0], qkv[1], qkv[2], qkv[3]));
    }

    // ACCV = v^T kwi -> av
    {
        const int iq2 = row4, jq = col8;
        u64 acc[4][2];
        #pragma unroll
        for (int r = 0; r < 4; r++) { acc[r][0] = 0; acc[r][1] = 0; }
        #pragma unroll
        for (int t = 0; t < DT_; t++) {
            float4 v4 = ld4(buf + BV + tg(t, iq2));
            ulonglong2 K2 = ldp(buf + BKWI + tg(t, jq));
            u64 v0 = pk2(v4.x, v4.x), v1 = pk2(v4.y, v4.y);
            u64 v2 = pk2(v4.z, v4.z), v3 = pk2(v4.w, v4.w);
            fma2(acc[0][0], v0, K2.x); fma2(acc[0][1], v0, K2.y);
            fma2(acc[1][0], v1, K2.x); fma2(acc[1][1], v1, K2.y);
            fma2(acc[2][0], v2, K2.x); fma2(acc[2][1], v2, K2.y);
            fma2(acc[3][0], v3, K2.x); fma2(acc[3][1], v3, K2.y);
        }
        #pragma unroll
        for (int r = 0; r < 4; r++) {
            ulonglong2 o; o.x = acc[r][0]; o.y = acc[r][1];
            stp(av + sg(4 * iq2 + r, jq), o);
        }
    }
}

__global__ __launch_bounds__(THREADS, 1)
void rwkv7_kernel(const float* __restrict__ gw, const float* __restrict__ gq,
                  const float* __restrict__ gk, const float* __restrict__ gv,
                  const float* __restrict__ ga, const float* __restrict__ gb,
                  const float* __restrict__ gs0, float* __restrict__ gy)
{
    extern __shared__ __align__(16) float sm[];

    const int bh  = blockIdx.x;
    const int b   = bh / H_;
    const int h   = bh % H_;
    const int tid = threadIdx.x;
    const bool is_prod = tid >= 256;
    const int pt = tid & 255;

    // consumer mappings
    const int w    = pt >> 5;
    const int tx   = (w & 3) * 4 + ((pt >> 3) & 3);      // y phase: t
    const int iq   = ((w >> 2) & 1) * 8 + (pt & 7);      // y phase: i-quad
    const int iq2  = pt >> 4;                             // update: i-quad
    const int jq   = pt & 15;                             // update: j-quad
    // mma mapping
    const int lane = pt & 31;
    const int mt   = w & 1;            // 0 = abu (wa rows), 1 = yp (wq rows)
    const int nb   = w >> 1;           // n-block: cols 16*nb .. 16*nb+15
    const int gid  = lane >> 2;
    const int tq   = lane & 3;

    // ---- bootstrap ----
    if (is_prod) {
        produce(sm, sm + OFF_BUF, sm + OFF_ACCV, gw, gq, gk, gv, ga, gb, b, h, 0, pt);
    } else {
        const float* s0p = gs0 + (size_t)bh * 4096;
        #pragma unroll
        for (int q4 = pt; q4 < 1024; q4 += 256) {
            int row = q4 >> 4, f = q4 & 15;
            st4(sm + OFF_S + row * 68 + f * 4, ld4(s0p + row * 64 + f * 4));
        }
    }
    __syncthreads();

    for (int ch = 0; ch < NT_; ch++) {
        const int p = ch & 1;

        if (is_prod) {
            if (ch + 1 < NT_)
                produce(sm, sm + OFF_BUF + (p ^ 1) * BUF_STRIDE,
                        sm + OFF_ACCV + (p ^ 1) * 4096,
                        gw, gq, gk, gv, ga, gb, b, h, ch + 1, pt);
        } else {
            float* buf = sm + OFF_BUF + p * BUF_STRIDE;
            float* av  = sm + OFF_ACCV + p * 4096;

            // ===== state GEMM via mma.sync tf32: D = [wa;wq] @ S^T =====
            {
                const float* Wr = buf + BWAQ + (16 * mt + gid) * 68;
                const int n0 = 16 * nb, n1 = n0 + 8;
                float4 C0 = {0.f, 0.f, 0.f, 0.f};
                float4 C1 = {0.f, 0.f, 0.f, 0.f};
                #pragma unroll
                for (int k = 0; k < 8; k++) {
                    const int ca = 8 * k + tq;
                    uint32_t a0 = __float_as_uint(Wr[ca]);
                    uint32_t a1 = __float_as_uint(Wr[8 * 68 + ca]);
                    uint32_t a2 = __float_as_uint(Wr[ca + 4]);
                    uint32_t a3 = __float_as_uint(Wr[8 * 68 + ca + 4]);
                    const float* S0 = sm + OFF_S + (n0 + gid) * 68 + ca;
                    const float* S1 = sm + OFF_S + (n1 + gid) * 68 + ca;
                    uint32_t b00 = __float_as_uint(S0[0]);
                    uint32_t b01 = __float_as_uint(S0[4]);
                    uint32_t b10 = __float_as_uint(S1[0]);
                    uint32_t b11 = __float_as_uint(S1[4]);
                    mma8(C0, a0, a1, a2, a3, b00, b01);
                    mma8(C1, a0, a1, a2, a3, b10, b11);
                }
                float* dst = (mt == 0) ? (sm + OFF_ABU) : (sm + OFF_YP);
                *reinterpret_cast<float2*>(dst + gid * 68 + n0 + 2 * tq)       = make_float2(C0.x, C0.y);
                *reinterpret_cast<float2*>(dst + (gid + 8) * 68 + n0 + 2 * tq) = make_float2(C0.z, C0.w);
                *reinterpret_cast<float2*>(dst + gid * 68 + n1 + 2 * tq)       = make_float2(C1.x, C1.y);
                *reinterpret_cast<float2*>(dst + (gid + 8) * 68 + n1 + 2 * tq) = make_float2(C1.z, C1.w);
            }
            BARC();   // abu/yp raw ready

            // ===== solve (I-ab) u = abu+AKV (64 columns, 2 warps) =====
            if (pt < 64) {
                const int c = pt;
                float uu[DT_];
                #pragma unroll
                for (int t = 0; t < DT_; t++)
                    uu[t] = sm[OFF_ABU + t * 68 + c] + buf[BAKV + t * 68 + c];
                #pragma unroll
                for (int t = 1; t < DT_; t++) {
                    float a0 = uu[t], a1 = 0.f, a2 = 0.f, a3 = 0.f;
                    const float* abr = buf + BAB + t * 16;
                    #pragma unroll
                    for (int s4 = 0; 4 * s4 < t; s4++) {
                        float4 abq = ld4(abr + 4 * s4);
                        int s = 4 * s4;
                        if (s     < t) a0 += abq.x * uu[s];
                        if (s + 1 < t) a1 += abq.y * uu[s + 1];
                        if (s + 2 < t) a2 += abq.z * uu[s + 2];
                        if (s + 3 < t) a3 += abq.w * uu[s + 3];
                    }
                    uu[t] = (a0 + a1) + (a2 + a3);
                }
                #pragma unroll
                for (int t = 0; t < DT_; t++) sm[OFF_U + tw(t, c)] = uu[t];
            }
            BARC();   // u ready

            // ===== y = yp + QKV + qb@u =====
            {
                float4 ypv = ld4(sm + OFF_YP + tx * 68 + 4 * iq);
                float4 qkv = ld4(buf + BQKV + tx * 68 + 4 * iq);
                float4 qbr[4];
                #pragma unroll
                for (int r = 0; r < 4; r++) qbr[r] = ld4(buf + BQB + tx * 16 + 4 * r);
                u64 y01 = pk2(ypv.x + qkv.x, ypv.y + qkv.y);
                u64 y23 = pk2(ypv.z + qkv.z, ypv.w + qkv.w);
                #pragma unroll
                for (int s = 0; s < 16; s++) {
                    float qbs = (s & 2) ? ((s & 1) ? qbr[s >> 2].w : qbr[s >> 2].z)
                                        : ((s & 1) ? qbr[s >> 2].y : qbr[s >> 2].x);
                    ulonglong2 U2 = ldp(sm + OFF_U + tg(s, iq));
                    u64 q2 = pk2(qbs, qbs);
                    fma2(y01, q2, U2.x);
                    fma2(y23, q2, U2.y);
                }
                float o0, o1, o2, o3;
                un2(y01, o0, o1); un2(y23, o2, o3);
                size_t yb = (((size_t)b * T_ + ch * DT_ + tx) * H_ + h) * C_ + 4 * iq;
                __stcs(reinterpret_cast<float4*>(gy + yb), make_float4(o0, o1, o2, o3));
            }

            // ===== state update: S = (S + accv + u^T bwi) * fw =====
            {
                u64 accR[4][2];
                #pragma unroll
                for (int r = 0; r < 4; r++) {
                    ulonglong2 A0 = ldp(av + sg(4 * iq2 + r, jq));
                    accR[r][0] = A0.x; accR[r][1] = A0.y;
                }
                #pragma unroll
                for (int t = 0; t < DT_; t++) {
                    float4 u4 = ld4(sm + OFF_U + tg(t, iq2));
                    ulonglong2 B2 = ldp(buf + BBWI + tg(t, jq));
                    u64 u0 = pk2(u4.x, u4.x), u1 = pk2(u4.y, u4.y);
                    u64 u2 = pk2(u4.z, u4.z), u3 = pk2(u4.w, u4.w);
                    fma2(accR[0][0], u0, B2.x); fma2(accR[0][1], u0, B2.y);
                    fma2(accR[1][0], u1, B2.x); fma2(accR[1][1], u1, B2.y);
                    fma2(accR[2][0], u2, B2.x); fma2(accR[2][1], u2, B2.y);
                    fma2(accR[3][0], u3, B2.x); fma2(accR[3][1], u3, B2.y);
                }
                ulonglong2 FWp = ldp(buf + BFW + 4 * jq);
                #pragma unroll
                for (int r = 0; r < 4; r++) {
                    float* sp = sm + OFF_S + (4 * iq2 + r) * 68 + 4 * jq;
                    ulonglong2 S = ldp(sp);
                    S.x = mul2(add2(S.x, accR[r][0]), FWp.x);
                    S.y = mul2(add2(S.y, accR[r][1]), FWp.y);
                    stp(sp, S);
                }
            }
        }
        __syncthreads();   // buffer handoff + S visibility
    }
}

extern "C" void kernel_launch(void* const* d_in, const int* in_sizes, int n_in,
                              void* d_out, int out_size)
{
    const float* w  = (const float*)d_in[0];
    const float* q  = (const float*)d_in[1];
    const float* k  = (const float*)d_in[2];
    const float* v  = (const float*)d_in[3];
    const float* a  = (const float*)d_in[4];
    const float* b  = (const float*)d_in[5];
    const float* s0 = (const float*)d_in[6];
    float* y = (float*)d_out;

    cudaFuncSetAttribute(rwkv7_kernel, cudaFuncAttributeMaxDynamicSharedMemorySize, SMEM_BYTES);
    rwkv7_kernel<<<B_ * H_, THREADS, SMEM_BYTES>>>(w, q, k, v, a, b, s0, y);
}

// round 12
// speedup vs baseline: 1.3613x; 1.1622x over previous
#include <cuda_runtime.h>
#include <cstdint>

// RWKV7 chunked attention, B=4 T=2048 H=32 C=64 dT=16.
// One CTA (512 thr) per (b,h). Producer/consumer pipeline.
// tf32 mma.sync for: consumer state GEMM [wa;wq]@S^T (R10) and
// producer grams D32 = [wa;wq]@[bwi;kwi]^T (R11, masks at writeback).

#define B_ 4
#define T_ 2048
#define H_ 32
#define C_ 64
#define DT_ 16
#define NT_ 128
#define THREADS 512

typedef unsigned long long u64;

// ---- shared layout (float words) ----
#define OFF_S    0          // [64][68] plain
#define OFF_U    4352       // [16][64] tg swizzle
#define OFF_ABU  5376       // [16][68] plain (raw state-GEMM out, wa rows)
#define OFF_YP   6464       // [16][68] plain (wq rows)
#define OFF_LPP  7552       // [4][64]
#define OFF_BUF  7808
// per-buffer offsets:
#define BWAQ 0              // [32][68] tf32 (rows 0-15 wa, 16-31 wq)
#define BKWQ 2176           // [32][68] tf32 (rows 0-15 bwi, 16-31 kwi)
#define BKWI 4352           // [16][64] exact, tg/tw swizzle
#define BBWI 5376
#define BV   6400
#define BAKV 7424           // [16][68] plain
#define BQKV 8512           // [16][68] plain
#define BD32 9600           // [32][36] masked grams: ab|ak / qb|qk
#define BFW  10752          // [64]
#define BUF_STRIDE 10816
#define OFF_ACCV (OFF_BUF + 2 * BUF_STRIDE)   // 2 x [64][64] sg swizzle
#define SMEM_WORDS (OFF_ACCV + 2 * 4096)
#define SMEM_BYTES (SMEM_WORDS * 4)

#define BARC() asm volatile("bar.sync 1, 256;" ::: "memory")   // consumer group
#define BARP() asm volatile("bar.sync 2, 256;" ::: "memory")   // producer group

// xor swizzles for [16][64] tiles
__device__ __forceinline__ int tg(int t, int f)  { return t * 64 + (((f ^ t) & 15) << 2); }
__device__ __forceinline__ int tw(int t, int c)  { return t * 64 + ((((c >> 2) ^ t) & 15) << 2) + (c & 3); }
// accv tile [64][64] swizzle
__device__ __forceinline__ int sg(int r, int f)  { return r * 64 + (((f ^ (r >> 2)) & 15) << 2); }

__device__ __forceinline__ float4 ld4(const float* p) { return *reinterpret_cast<const float4*>(p); }
__device__ __forceinline__ void st4(float* p, float4 v) { *reinterpret_cast<float4*>(p) = v; }
__device__ __forceinline__ ulonglong2 ldp(const float* p) { return *reinterpret_cast<const ulonglong2*>(p); }
__device__ __forceinline__ void stp(float* p, ulonglong2 v) { *reinterpret_cast<ulonglong2*>(p) = v; }

__device__ __forceinline__ u64 pk2(float lo, float hi) {
    u64 r; asm("mov.b64 %0, {%1, %2};" : "=l"(r) : "f"(lo), "f"(hi)); return r;
}
__device__ __forceinline__ void un2(u64 v, float& lo, float& hi) {
    asm("mov.b64 {%0, %1}, %2;" : "=f"(lo), "=f"(hi) : "l"(v));
}
__device__ __forceinline__ void fma2(u64& d, u64 a, u64 b) {
    asm("fma.rn.f32x2 %0, %1, %2, %0;" : "+l"(d) : "l"(a), "l"(b));
}
__device__ __forceinline__ u64 add2(u64 a, u64 b) {
    u64 d; asm("add.rn.f32x2 %0, %1, %2;" : "=l"(d) : "l"(a), "l"(b)); return d;
}
__device__ __forceinline__ u64 mul2(u64 a, u64 b) {
    u64 d; asm("mul.rn.f32x2 %0, %1, %2;" : "=l"(d) : "l"(a), "l"(b)); return d;
}
__device__ __forceinline__ float tf32r(float x) {
    uint32_t r; asm("cvt.rna.tf32.f32 %0, %1;" : "=r"(r) : "f"(x));
    return __uint_as_float(r);
}
__device__ __forceinline__ void mma8(float4& d, uint32_t a0, uint32_t a1, uint32_t a2,
                                     uint32_t a3, uint32_t b0, uint32_t b1) {
    asm volatile(
        "mma.sync.aligned.m16n8k8.row.col.f32.tf32.tf32.f32 "
        "{%0,%1,%2,%3}, {%4,%5,%6,%7}, {%8,%9}, {%0,%1,%2,%3};"
        : "+f"(d.x), "+f"(d.y), "+f"(d.z), "+f"(d.w)
        : "r"(a0), "r"(a1), "r"(a2), "r"(a3), "r"(b0), "r"(b1));
}

// ---------- producer: stage chunk cp into buf, accv into av ----------
__device__ __forceinline__ void produce(
    float* __restrict__ sm, float* __restrict__ buf, float* __restrict__ av,
    const float* __restrict__ gw, const float* __restrict__ gq,
    const float* __restrict__ gk, const float* __restrict__ gv,
    const float* __restrict__ ga, const float* __restrict__ gb,
    int b, int h, int cp, int pt)
{
    const int th = pt >> 6;
    const int cl = pt & 63;
    const size_t strT = (size_t)H_ * C_;
    const int wmp  = pt >> 5;
    const int row4 = (wmp & 3) * 4 + ((pt >> 3) & 3);
    const int col8 = ((wmp >> 2) & 1) * 8 + (pt & 7);
    const int lane = pt & 31;
    const int gid  = lane >> 2;
    const int tq   = lane & 3;

    // load + decay + stage
    {
        size_t base = (((size_t)b * T_ + cp * DT_ + 4 * th) * H_ + h) * C_ + cl;
        float rw[4], rq[4], rk[4], rv[4], ra[4], rb[4];
        #pragma unroll
        for (int r = 0; r < 4; r++) {
            size_t ix = base + (size_t)r * strT;
            rw[r] = gw[ix]; rq[r] = gq[ix]; rk[r] = gk[ix];
            rv[r] = gv[ix]; ra[r] = ga[ix]; rb[r] = gb[ix];
        }
        float wd[4]; float lp = 1.f;
        #pragma unroll
        for (int r = 0; r < 4; r++) { wd[r] = __expf(-__expf(rw[r])); lp *= wd[r]; }
        sm[OFF_LPP + th * 64 + cl] = lp;
        BARP();
        float incl = 1.f;
        #pragma unroll
        for (int gg = 0; gg < 3; gg++)
            if (gg < th) incl *= sm[OFF_LPP + gg * 64 + cl];
        #pragma unroll
        for (int r = 0; r < 4; r++) {
            int t = 4 * th + r;
            float ip = incl; incl *= wd[r];
            float rinv = __fdividef(1.f, incl);
            float kw = rk[r] * rinv;
            float bw = rb[r] * rinv;
            int twd = tw(t, cl);
            buf[BWAQ + t * 68 + cl]        = tf32r(ra[r] * ip);     // wa
            buf[BWAQ + (16 + t) * 68 + cl] = tf32r(rq[r] * incl);   // wq
            buf[BKWQ + t * 68 + cl]        = tf32r(bw);             // bwi (tf32)
            buf[BKWQ + (16 + t) * 68 + cl] = tf32r(kw);             // kwi (tf32)
            buf[BKWI + twd] = kw;
            buf[BBWI + twd] = bw;
            buf[BV   + twd] = rv[r];
        }
        if (th == 3) buf[BFW + cl] = incl;
    }
    BARP();

    // ===== grams via mma: D32 = [wa;wq] @ [bwi;kwi]^T, masked at writeback =====
    {
        const int mt = wmp & 1;          // 0: wa rows (strict), 1: wq rows (incl)
        const int nb = wmp >> 1;         // n-block of 8 cols
        const float* Ar = buf + BWAQ + (16 * mt + gid) * 68;
        const float* Br = buf + BKWQ + (8 * nb + gid) * 68;
        float4 Cv = {0.f, 0.f, 0.f, 0.f};
        #pragma unroll
        for (int k = 0; k < 8; k++) {
            const int ca = 8 * k + tq;
            uint32_t a0 = __float_as_uint(Ar[ca]);
            uint32_t a1 = __float_as_uint(Ar[8 * 68 + ca]);
            uint32_t a2 = __float_as_uint(Ar[ca + 4]);
            uint32_t a3 = __float_as_uint(Ar[8 * 68 + ca + 4]);
            uint32_t b0 = __float_as_uint(Br[ca]);
            uint32_t b1 = __float_as_uint(Br[ca + 4]);
            mma8(Cv, a0, a1, a2, a3, b0, b1);
        }
        const int t0 = gid, t1 = gid + 8;
        const int C0 = 8 * nb + 2 * tq, C1 = C0 + 1;
        const int s0 = C0 & 15, s1 = C1 & 15;
        float m00, m01, m10, m11;
        if (mt == 0) {   // strict
            m00 = (t0 > s0) ? 1.f : 0.f;  m01 = (t0 > s1) ? 1.f : 0.f;
            m10 = (t1 > s0) ? 1.f : 0.f;  m11 = (t1 > s1) ? 1.f : 0.f;
        } else {         // inclusive
            m00 = (t0 >= s0) ? 1.f : 0.f; m01 = (t0 >= s1) ? 1.f : 0.f;
            m10 = (t1 >= s0) ? 1.f : 0.f; m11 = (t1 >= s1) ? 1.f : 0.f;
        }
        float* D = buf + BD32;
        D[(16 * mt + gid)     * 36 + C0] = Cv.x * m00;
        D[(16 * mt + gid)     * 36 + C1] = Cv.y * m01;
        D[(16 * mt + gid + 8) * 36 + C0] = Cv.z * m10;
        D[(16 * mt + gid + 8) * 36 + C1] = Cv.w * m11;
    }
    BARP();

    // AKV = ak@v, QKV = qk@v  (ak/qk read from D32)
    {
        const int t = row4, iq = col8;
        u64 acc[4] = {0, 0, 0, 0};
        #pragma unroll
        for (int s = 0; s < 16; s++) {
            float akv_ = buf[BD32 + t * 36 + 16 + s];           // ak(t,s)
            float qkv_ = buf[BD32 + (16 + t) * 36 + 16 + s];    // qk(t,s)
            u64 akqk = pk2(akv_, qkv_);
            float4 v4 = ld4(buf + BV + tg(s, iq));
            fma2(acc[0], akqk, pk2(v4.x, v4.x));
            fma2(acc[1], akqk, pk2(v4.y, v4.y));
            fma2(acc[2], akqk, pk2(v4.z, v4.z));
            fma2(acc[3], akqk, pk2(v4.w, v4.w));
        }
        float akv[4], qkv[4];
        #pragma unroll
        for (int r = 0; r < 4; r++) un2(acc[r], akv[r], qkv[r]);
        st4(buf + BAKV + t * 68 + 4 * iq, make_float4(akv[0], akv[1], akv[2], akv[3]));
        st4(buf + BQKV + t * 68 + 4 * iq, make_float4(qkv[0], qkv[1], qkv[2], qkv[3]));
    }

    // ACCV = v^T kwi -> av (exact)
    {
        const int iq2 = row4, jq = col8;
        u64 acc[4][2];
        #pragma unroll
        for (int r = 0; r < 4; r++) { acc[r][0] = 0; acc[r][1] = 0; }
        #pragma unroll
        for (int t = 0; t < DT_; t++) {
            float4 v4 = ld4(buf + BV + tg(t, iq2));
            ulonglong2 K2 = ldp(buf + BKWI + tg(t, jq));
            u64 v0 = pk2(v4.x, v4.x), v1 = pk2(v4.y, v4.y);
            u64 v2 = pk2(v4.z, v4.z), v3 = pk2(v4.w, v4.w);
            fma2(acc[0][0], v0, K2.x); fma2(acc[0][1], v0, K2.y);
            fma2(acc[1][0], v1, K2.x); fma2(acc[1][1], v1, K2.y);
            fma2(acc[2][0], v2, K2.x); fma2(acc[2][1], v2, K2.y);
            fma2(acc[3][0], v3, K2.x); fma2(acc[3][1], v3, K2.y);
        }
        #pragma unroll
        for (int r = 0; r < 4; r++) {
            ulonglong2 o; o.x = acc[r][0]; o.y = acc[r][1];
            stp(av + sg(4 * iq2 + r, jq), o);
        }
    }
}

__global__ __launch_bounds__(THREADS, 1)
void rwkv7_kernel(const float* __restrict__ gw, const float* __restrict__ gq,
                  const float* __restrict__ gk, const float* __restrict__ gv,
                  const float* __restrict__ ga, const float* __restrict__ gb,
                  const float* __restrict__ gs0, float* __restrict__ gy)
{
    extern __shared__ __align__(16) float sm[];

    const int bh  = blockIdx.x;
    const int b   = bh / H_;
    const int h   = bh % H_;
    const int tid = threadIdx.x;
    const bool is_prod = tid >= 256;
    const int pt = tid & 255;

    // consumer mappings
    const int w    = pt >> 5;
    const int tx   = (w & 3) * 4 + ((pt >> 3) & 3);
    const int iq   = ((w >> 2) & 1) * 8 + (pt & 7);
    const int iq2  = pt >> 4;
    const int jq   = pt & 15;
    const int lane = pt & 31;
    const int mt   = w & 1;
    const int nb   = w >> 1;
    const int gid  = lane >> 2;
    const int tq   = lane & 3;

    // ---- bootstrap ----
    if (is_prod) {
        produce(sm, sm + OFF_BUF, sm + OFF_ACCV, gw, gq, gk, gv, ga, gb, b, h, 0, pt);
    } else {
        const float* s0p = gs0 + (size_t)bh * 4096;
        #pragma unroll
        for (int q4 = pt; q4 < 1024; q4 += 256) {
            int row = q4 >> 4, f = q4 & 15;
            st4(sm + OFF_S + row * 68 + f * 4, ld4(s0p + row * 64 + f * 4));
        }
    }
    __syncthreads();

    for (int ch = 0; ch < NT_; ch++) {
        const int p = ch & 1;

        if (is_prod) {
            if (ch + 1 < NT_)
                produce(sm, sm + OFF_BUF + (p ^ 1) * BUF_STRIDE,
                        sm + OFF_ACCV + (p ^ 1) * 4096,
                        gw, gq, gk, gv, ga, gb, b, h, ch + 1, pt);
        } else {
            float* buf = sm + OFF_BUF + p * BUF_STRIDE;
            float* av  = sm + OFF_ACCV + p * 4096;

            // ===== state GEMM via mma.sync tf32: D = [wa;wq] @ S^T =====
            {
                const float* Wr = buf + BWAQ + (16 * mt + gid) * 68;
                const int n0 = 16 * nb, n1 = n0 + 8;
                float4 C0 = {0.f, 0.f, 0.f, 0.f};
                float4 C1 = {0.f, 0.f, 0.f, 0.f};
                #pragma unroll
                for (int k = 0; k < 8; k++) {
                    const int ca = 8 * k + tq;
                    uint32_t a0 = __float_as_uint(Wr[ca]);
                    uint32_t a1 = __float_as_uint(Wr[8 * 68 + ca]);
                    uint32_t a2 = __float_as_uint(Wr[ca + 4]);
                    uint32_t a3 = __float_as_uint(Wr[8 * 68 + ca + 4]);
                    const float* S0 = sm + OFF_S + (n0 + gid) * 68 + ca;
                    const float* S1 = sm + OFF_S + (n1 + gid) * 68 + ca;
                    uint32_t b00 = __float_as_uint(S0[0]);
                    uint32_t b01 = __float_as_uint(S0[4]);
                    uint32_t b10 = __float_as_uint(S1[0]);
                    uint32_t b11 = __float_as_uint(S1[4]);
                    mma8(C0, a0, a1, a2, a3, b00, b01);
                    mma8(C1, a0, a1, a2, a3, b10, b11);
                }
                float* dst = (mt == 0) ? (sm + OFF_ABU) : (sm + OFF_YP);
                *reinterpret_cast<float2*>(dst + gid * 68 + n0 + 2 * tq)       = make_float2(C0.x, C0.y);
                *reinterpret_cast<float2*>(dst + (gid + 8) * 68 + n0 + 2 * tq) = make_float2(C0.z, C0.w);
                *reinterpret_cast<float2*>(dst + gid * 68 + n1 + 2 * tq)       = make_float2(C1.x, C1.y);
                *reinterpret_cast<float2*>(dst + (gid + 8) * 68 + n1 + 2 * tq) = make_float2(C1.z, C1.w);
            }
            BARC();   // abu/yp raw ready

            // ===== solve (I-ab) u = abu+AKV (64 columns, 2 warps) =====
            if (pt < 64) {
                const int c = pt;
                float uu[DT_];
                #pragma unroll
                for (int t = 0; t < DT_; t++)
                    uu[t] = sm[OFF_ABU + t * 68 + c] + buf[BAKV + t * 68 + c];
                #pragma unroll
                for (int t = 1; t < DT_; t++) {
                    float a0 = uu[t], a1 = 0.f, a2 = 0.f, a3 = 0.f;
                    const float* abr = buf + BD32 + t * 36;     // ab row (masked)
                    #pragma unroll
                    for (int s4 = 0; 4 * s4 < t; s4++) {
                        float4 abq = ld4(abr + 4 * s4);
                        int s = 4 * s4;
                        if (s     < t) a0 += abq.x * uu[s];
                        if (s + 1 < t) a1 += abq.y * uu[s + 1];
                        if (s + 2 < t) a2 += abq.z * uu[s + 2];
                        if (s + 3 < t) a3 += abq.w * uu[s + 3];
                    }
                    uu[t] = (a0 + a1) + (a2 + a3);
                }
                #pragma unroll
                for (int t = 0; t < DT_; t++) sm[OFF_U + tw(t, c)] = uu[t];
            }
            BARC();   // u ready

            // ===== y = yp + QKV + qb@u =====
            {
                float4 ypv = ld4(sm + OFF_YP + tx * 68 + 4 * iq);
                float4 qkv = ld4(buf + BQKV + tx * 68 + 4 * iq);
                float4 qbr[4];
                #pragma unroll
                for (int r = 0; r < 4; r++)
                    qbr[r] = ld4(buf + BD32 + (16 + tx) * 36 + 4 * r);   // qb row
                u64 y01 = pk2(ypv.x + qkv.x, ypv.y + qkv.y);
                u64 y23 = pk2(ypv.z + qkv.z, ypv.w + qkv.w);
                #pragma unroll
                for (int s = 0; s < 16; s++) {
                    float qbs = (s & 2) ? ((s & 1) ? qbr[s >> 2].w : qbr[s >> 2].z)
                                        : ((s & 1) ? qbr[s >> 2].y : qbr[s >> 2].x);
                    ulonglong2 U2 = ldp(sm + OFF_U + tg(s, iq));
                    u64 q2 = pk2(qbs, qbs);
                    fma2(y01, q2, U2.x);
                    fma2(y23, q2, U2.y);
                }
                float o0, o1, o2, o3;
                un2(y01, o0, o1); un2(y23, o2, o3);
                size_t yb = (((size_t)b * T_ + ch * DT_ + tx) * H_ + h) * C_ + 4 * iq;
                __stcs(reinterpret_cast<float4*>(gy + yb), make_float4(o0, o1, o2, o3));
            }

            // ===== state update: S = (S + accv + u^T bwi) * fw =====
            {
                u64 accR[4][2];
                #pragma unroll
                for (int r = 0; r < 4; r++) {
                    ulonglong2 A0 = ldp(av + sg(4 * iq2 + r, jq));
                    accR[r][0] = A0.x; accR[r][1] = A0.y;
                }
                #pragma unroll
                for (int t = 0; t < DT_; t++) {
                    float4 u4 = ld4(sm + OFF_U + tg(t, iq2));
                    ulonglong2 B2 = ldp(buf + BBWI + tg(t, jq));
                    u64 u0 = pk2(u4.x, u4.x), u1 = pk2(u4.y, u4.y);
                    u64 u2 = pk2(u4.z, u4.z), u3 = pk2(u4.w, u4.w);
                    fma2(accR[0][0], u0, B2.x); fma2(accR[0][1], u0, B2.y);
                    fma2(accR[1][0], u1, B2.x); fma2(accR[1][1], u1, B2.y);
                    fma2(accR[2][0], u2, B2.x); fma2(accR[2][1], u2, B2.y);
                    fma2(accR[3][0], u3, B2.x); fma2(accR[3][1], u3, B2.y);
                }
                ulonglong2 FWp = ldp(buf + BFW + 4 * jq);
                #pragma unroll
                for (int r = 0; r < 4; r++) {
                    float* sp = sm + OFF_S + (4 * iq2 + r) * 68 + 4 * jq;
                    ulonglong2 S = ldp(sp);
                    S.x = mul2(add2(S.x, accR[r][0]), FWp.x);
                    S.y = mul2(add2(S.y, accR[r][1]), FWp.y);
                    stp(sp, S);
                }
            }
        }
        __syncthreads();   // buffer handoff + S visibility
    }
}

extern "C" void kernel_launch(void* const* d_in, const int* in_sizes, int n_in,
                              void* d_out, int out_size)
{
    const float* w  = (const float*)d_in[0];
    const float* q  = (const float*)d_in[1];
    const float* k  = (const float*)d_in[2];
    const float* v  = (const float*)d_in[3];
    const float* a  = (const float*)d_in[4];
    const float* b  = (const float*)d_in[5];
    const float* s0 = (const float*)d_in[6];
    float* y = (float*)d_out;

    cudaFuncSetAttribute(rwkv7_kernel, cudaFuncAttributeMaxDynamicSharedMemorySize, SMEM_BYTES);
    rwkv7_kernel<<<B_ * H_, THREADS, SMEM_BYTES>>>(w, q, k, v, a, b, s0, y);
}

// round 13
// speedup vs baseline: 1.5286x; 1.1229x over previous
#include <cuda_runtime.h>
#include <cstdint>

// RWKV7 chunked attention, B=4 T=2048 H=32 C=64 dT=16.
// One CTA (512 thr) per (b,h). Producer/consumer pipeline.
// tf32 mma.sync for: state GEMM [wa;wq]@S^T, grams [wa;wq]@[bwi;kwi]^T,
// AKV/QKV [ak;qk]@v, ACCV v^T@kwi, ACCU u^T@bwi (R12).

#define B_ 4
#define T_ 2048
#define H_ 32
#define C_ 64
#define DT_ 16
#define NT_ 128
#define THREADS 512

typedef unsigned long long u64;

// ---- shared layout (float words) ----
#define OFF_S    0          // [64][68] plain
#define OFF_U    4352       // [16][64] tg swizzle (exact u, for y)
#define OFF_UT   5376       // [64][17] tf32 u^T (for ACCU mma)
#define OFF_ABU  6464       // [16][68] plain
#define OFF_YP   7552       // [16][68] plain
#define OFF_LPP  8640       // [4][64]
#define OFF_BUF  8896
// per-buffer offsets:
#define BWAQ 0              // [32][68] tf32 (wa rows 0-15, wq rows 16-31)
#define BKWQ 2176           // [32][68] tf32 (bwi rows 0-15, kwi rows 16-31)
#define BVT  4352           // [64][17] tf32 v^T  (VT[i][t])
#define BKWT 5440           // [64][17] tf32 kwi^T (KWT[j][t])
#define BBWT 6528           // [64][17] tf32 bwi^T (BWT[j][t])
#define BAKV 7616           // [16][68] plain
#define BQKV 8704           // [16][68] plain
#define BD32 9792           // [32][36] masked grams (tf32): ab|ak / qb|qk
#define BFW  10944          // [64]
#define BUF_STRIDE 11008
#define OFF_ACCV (OFF_BUF + 2 * BUF_STRIDE)   // 2 x [64][68] plain (raw accv)
#define SMEM_WORDS (OFF_ACCV + 2 * 4352)
#define SMEM_BYTES (SMEM_WORDS * 4)

#define BARC() asm volatile("bar.sync 1, 256;" ::: "memory")   // consumer group
#define BARP() asm volatile("bar.sync 2, 256;" ::: "memory")   // producer group

// xor swizzle for [16][64] tile (u in tg layout for y phase)
__device__ __forceinline__ int tg(int t, int f)  { return t * 64 + (((f ^ t) & 15) << 2); }
__device__ __forceinline__ int tw(int t, int c)  { return t * 64 + ((((c >> 2) ^ t) & 15) << 2) + (c & 3); }

__device__ __forceinline__ float4 ld4(const float* p) { return *reinterpret_cast<const float4*>(p); }
__device__ __forceinline__ void st4(float* p, float4 v) { *reinterpret_cast<float4*>(p) = v; }
__device__ __forceinline__ ulonglong2 ldp(const float* p) { return *reinterpret_cast<const ulonglong2*>(p); }

__device__ __forceinline__ u64 pk2(float lo, float hi) {
    u64 r; asm("mov.b64 %0, {%1, %2};" : "=l"(r) : "f"(lo), "f"(hi)); return r;
}
__device__ __forceinline__ void un2(u64 v, float& lo, float& hi) {
    asm("mov.b64 {%0, %1}, %2;" : "=f"(lo), "=f"(hi) : "l"(v));
}
__device__ __forceinline__ void fma2(u64& d, u64 a, u64 b) {
    asm("fma.rn.f32x2 %0, %1, %2, %0;" : "+l"(d) : "l"(a), "l"(b));
}
__device__ __forceinline__ float tf32r(float x) {
    uint32_t r; asm("cvt.rna.tf32.f32 %0, %1;" : "=r"(r) : "f"(x));
    return __uint_as_float(r);
}
__device__ __forceinline__ void mma8(float4& d, uint32_t a0, uint32_t a1, uint32_t a2,
                                     uint32_t a3, uint32_t b0, uint32_t b1) {
    asm volatile(
        "mma.sync.aligned.m16n8k8.row.col.f32.tf32.tf32.f32 "
        "{%0,%1,%2,%3}, {%4,%5,%6,%7}, {%8,%9}, {%0,%1,%2,%3};"
        : "+f"(d.x), "+f"(d.y), "+f"(d.z), "+f"(d.w)
        : "r"(a0), "r"(a1), "r"(a2), "r"(a3), "r"(b0), "r"(b1));
}
__device__ __forceinline__ uint32_t fu(float x) { return __float_as_uint(x); }

// ---------- producer ----------
__device__ __forceinline__ void produce(
    float* __restrict__ sm, float* __restrict__ buf, float* __restrict__ av,
    const float* __restrict__ gw, const float* __restrict__ gq,
    const float* __restrict__ gk, const float* __restrict__ gv,
    const float* __restrict__ ga, const float* __restrict__ gb,
    int b, int h, int cp, int pt)
{
    const int th = pt >> 6;
    const int cl = pt & 63;
    const size_t strT = (size_t)H_ * C_;
    const int wmp  = pt >> 5;
    const int lane = pt & 31;
    const int gid  = lane >> 2;
    const int tq   = lane & 3;

    // ---- stage: load, decay, write row-major + transposed tf32 tiles ----
    {
        size_t base = (((size_t)b * T_ + cp * DT_ + 4 * th) * H_ + h) * C_ + cl;
        float rw[4], rq[4], rk[4], rv[4], ra[4], rb[4];
        #pragma unroll
        for (int r = 0; r < 4; r++) {
            size_t ix = base + (size_t)r * strT;
            rw[r] = gw[ix]; rq[r] = gq[ix]; rk[r] = gk[ix];
            rv[r] = gv[ix]; ra[r] = ga[ix]; rb[r] = gb[ix];
        }
        float wd[4]; float lp = 1.f;
        #pragma unroll
        for (int r = 0; r < 4; r++) { wd[r] = __expf(-__expf(rw[r])); lp *= wd[r]; }
        sm[OFF_LPP + th * 64 + cl] = lp;
        BARP();
        float incl = 1.f;
        #pragma unroll
        for (int gg = 0; gg < 3; gg++)
            if (gg < th) incl *= sm[OFF_LPP + gg * 64 + cl];
        #pragma unroll
        for (int r = 0; r < 4; r++) {
            int t = 4 * th + r;
            float ip = incl; incl *= wd[r];
            float rinv = __fdividef(1.f, incl);
            float kw = tf32r(rk[r] * rinv);
            float bw = tf32r(rb[r] * rinv);
            buf[BWAQ + t * 68 + cl]        = tf32r(ra[r] * ip);
            buf[BWAQ + (16 + t) * 68 + cl] = tf32r(rq[r] * incl);
            buf[BKWQ + t * 68 + cl]        = bw;
            buf[BKWQ + (16 + t) * 68 + cl] = kw;
            buf[BVT  + cl * 17 + t] = tf32r(rv[r]);
            buf[BKWT + cl * 17 + t] = kw;
            buf[BBWT + cl * 17 + t] = bw;
        }
        if (th == 3) buf[BFW + cl] = incl;
    }
    BARP();

    // ---- grams via mma: D32 = [wa;wq] @ [bwi;kwi]^T, masked+tf32 at writeback ----
    {
        const int mt = wmp & 1;
        const int nb = wmp >> 1;
        const float* Ar = buf + BWAQ + (16 * mt + gid) * 68;
        const float* Br = buf + BKWQ + (8 * nb + gid) * 68;
        float4 Cv = {0.f, 0.f, 0.f, 0.f};
        #pragma unroll
        for (int k = 0; k < 8; k++) {
            const int ca = 8 * k + tq;
            mma8(Cv, fu(Ar[ca]), fu(Ar[8 * 68 + ca]), fu(Ar[ca + 4]), fu(Ar[8 * 68 + ca + 4]),
                 fu(Br[ca]), fu(Br[ca + 4]));
        }
        const int t0 = gid, t1 = gid + 8;
        const int C0 = 8 * nb + 2 * tq, C1 = C0 + 1;
        const int s0 = C0 & 15, s1 = C1 & 15;
        float m00, m01, m10, m11;
        if (mt == 0) { m00 = (t0 > s0); m01 = (t0 > s1); m10 = (t1 > s0); m11 = (t1 > s1); }
        else         { m00 = (t0 >= s0); m01 = (t0 >= s1); m10 = (t1 >= s0); m11 = (t1 >= s1); }
        float* D = buf + BD32;
        D[(16 * mt + gid)     * 36 + C0] = tf32r(Cv.x * m00);
        D[(16 * mt + gid)     * 36 + C1] = tf32r(Cv.y * m01);
        D[(16 * mt + gid + 8) * 36 + C0] = tf32r(Cv.z * m10);
        D[(16 * mt + gid + 8) * 36 + C1] = tf32r(Cv.w * m11);
    }
    BARP();

    // ---- AKV/QKV via mma: [ak;qk](32x16) @ v(16x64) ----
    {
        const int mt = wmp & 1;                 // 0 -> akv, 1 -> qkv
        const int n0 = 16 * (wmp >> 1);         // tiles n0, n0+8
        const float* Ar = buf + BD32 + (16 * mt + gid) * 36 + 16;   // ak/qk rows
        float4 C0v = {0.f, 0.f, 0.f, 0.f};
        float4 C1v = {0.f, 0.f, 0.f, 0.f};
        #pragma unroll
        for (int k = 0; k < 2; k++) {
            const int ca = 8 * k + tq;
            uint32_t a0 = fu(Ar[ca]), a1 = fu(Ar[8 * 36 + ca]);
            uint32_t a2 = fu(Ar[ca + 4]), a3 = fu(Ar[8 * 36 + ca + 4]);
            uint32_t b00 = fu(buf[BVT + (n0 + gid) * 17 + ca]);
            uint32_t b01 = fu(buf[BVT + (n0 + gid) * 17 + ca + 4]);
            uint32_t b10 = fu(buf[BVT + (n0 + 8 + gid) * 17 + ca]);
            uint32_t b11 = fu(buf[BVT + (n0 + 8 + gid) * 17 + ca + 4]);
            mma8(C0v, a0, a1, a2, a3, b00, b01);
            mma8(C1v, a0, a1, a2, a3, b10, b11);
        }
        float* dst = buf + (mt == 0 ? BAKV : BQKV);
        *reinterpret_cast<float2*>(dst + gid * 68 + n0 + 2 * tq)           = make_float2(C0v.x, C0v.y);
        *reinterpret_cast<float2*>(dst + (gid + 8) * 68 + n0 + 2 * tq)     = make_float2(C0v.z, C0v.w);
        *reinterpret_cast<float2*>(dst + gid * 68 + n0 + 8 + 2 * tq)       = make_float2(C1v.x, C1v.y);
        *reinterpret_cast<float2*>(dst + (gid + 8) * 68 + n0 + 8 + 2 * tq) = make_float2(C1v.z, C1v.w);
    }

    // ---- ACCV via mma: v^T(64x16) @ kwi(16x64) -> av raw [64][68] ----
    {
        const int m0 = 16 * (wmp >> 1);
        const int nbase = 32 * (wmp & 1);
        float4 Cv[4] = {{0,0,0,0}, {0,0,0,0}, {0,0,0,0}, {0,0,0,0}};
        #pragma unroll
        for (int k = 0; k < 2; k++) {
            const int ca = 8 * k + tq;
            uint32_t a0 = fu(buf[BVT + (m0 + gid) * 17 + ca]);
            uint32_t a1 = fu(buf[BVT + (m0 + gid + 8) * 17 + ca]);
            uint32_t a2 = fu(buf[BVT + (m0 + gid) * 17 + ca + 4]);
            uint32_t a3 = fu(buf[BVT + (m0 + gid + 8) * 17 + ca + 4]);
            #pragma unroll
            for (int j = 0; j < 4; j++) {
                const int n = nbase + 8 * j;
                uint32_t b0 = fu(buf[BKWT + (n + gid) * 17 + ca]);
                uint32_t b1 = fu(buf[BKWT + (n + gid) * 17 + ca + 4]);
                mma8(Cv[j], a0, a1, a2, a3, b0, b1);
            }
        }
        #pragma unroll
        for (int j = 0; j < 4; j++) {
            const int n = nbase + 8 * j;
            *reinterpret_cast<float2*>(av + (m0 + gid) * 68 + n + 2 * tq)     = make_float2(Cv[j].x, Cv[j].y);
            *reinterpret_cast<float2*>(av + (m0 + gid + 8) * 68 + n + 2 * tq) = make_float2(Cv[j].z, Cv[j].w);
        }
    }
}

__global__ __launch_bounds__(THREADS, 1)
void rwkv7_kernel(const float* __restrict__ gw, const float* __restrict__ gq,
                  const float* __restrict__ gk, const float* __restrict__ gv,
                  const float* __restrict__ ga, const float* __restrict__ gb,
                  const float* __restrict__ gs0, float* __restrict__ gy)
{
    extern __shared__ __align__(16) float sm[];

    const int bh  = blockIdx.x;
    const int b   = bh / H_;
    const int h   = bh % H_;
    const int tid = threadIdx.x;
    const bool is_prod = tid >= 256;
    const int pt = tid & 255;

    // consumer mappings
    const int w    = pt >> 5;
    const int tx   = (w & 3) * 4 + ((pt >> 3) & 3);   // y phase: t
    const int iq   = ((w >> 2) & 1) * 8 + (pt & 7);   // y phase: i-quad
    const int lane = pt & 31;
    const int mt   = w & 1;
    const int nb   = w >> 1;
    const int gid  = lane >> 2;
    const int tq   = lane & 3;

    // ---- bootstrap ----
    if (is_prod) {
        produce(sm, sm + OFF_BUF, sm + OFF_ACCV, gw, gq, gk, gv, ga, gb, b, h, 0, pt);
    } else {
        const float* s0p = gs0 + (size_t)bh * 4096;
        #pragma unroll
        for (int q4 = pt; q4 < 1024; q4 += 256) {
            int row = q4 >> 4, f = q4 & 15;
            st4(sm + OFF_S + row * 68 + f * 4, ld4(s0p + row * 64 + f * 4));
        }
    }
    __syncthreads();

    for (int ch = 0; ch < NT_; ch++) {
        const int p = ch & 1;

        if (is_prod) {
            if (ch + 1 < NT_)
                produce(sm, sm + OFF_BUF + (p ^ 1) * BUF_STRIDE,
                        sm + OFF_ACCV + (p ^ 1) * 4352,
                        gw, gq, gk, gv, ga, gb, b, h, ch + 1, pt);
        } else {
            float* buf = sm + OFF_BUF + p * BUF_STRIDE;
            float* av  = sm + OFF_ACCV + p * 4352;

            // ===== state GEMM via mma: D = [wa;wq] @ S^T =====
            {
                const float* Wr = buf + BWAQ + (16 * mt + gid) * 68;
                const int n0 = 16 * nb, n1 = n0 + 8;
                float4 C0 = {0.f, 0.f, 0.f, 0.f};
                float4 C1 = {0.f, 0.f, 0.f, 0.f};
                #pragma unroll
                for (int k = 0; k < 8; k++) {
                    const int ca = 8 * k + tq;
                    uint32_t a0 = fu(Wr[ca]), a1 = fu(Wr[8 * 68 + ca]);
                    uint32_t a2 = fu(Wr[ca + 4]), a3 = fu(Wr[8 * 68 + ca + 4]);
                    const float* S0 = sm + OFF_S + (n0 + gid) * 68 + ca;
                    const float* S1 = sm + OFF_S + (n1 + gid) * 68 + ca;
                    mma8(C0, a0, a1, a2, a3, fu(S0[0]), fu(S0[4]));
                    mma8(C1, a0, a1, a2, a3, fu(S1[0]), fu(S1[4]));
                }
                float* dst = (mt == 0) ? (sm + OFF_ABU) : (sm + OFF_YP);
                *reinterpret_cast<float2*>(dst + gid * 68 + n0 + 2 * tq)       = make_float2(C0.x, C0.y);
                *reinterpret_cast<float2*>(dst + (gid + 8) * 68 + n0 + 2 * tq) = make_float2(C0.z, C0.w);
                *reinterpret_cast<float2*>(dst + gid * 68 + n1 + 2 * tq)       = make_float2(C1.x, C1.y);
                *reinterpret_cast<float2*>(dst + (gid + 8) * 68 + n1 + 2 * tq) = make_float2(C1.z, C1.w);
            }
            BARC();   // abu/yp raw ready

            // ===== solve (I-ab) u = abu+AKV (64 columns, 2 warps) =====
            if (pt < 64) {
                const int c = pt;
                float uu[DT_];
                #pragma unroll
                for (int t = 0; t < DT_; t++)
                    uu[t] = sm[OFF_ABU + t * 68 + c] + buf[BAKV + t * 68 + c];
                #pragma unroll
                for (int t = 1; t < DT_; t++) {
                    float a0 = uu[t], a1 = 0.f, a2 = 0.f, a3 = 0.f;
                    const float* abr = buf + BD32 + t * 36;
                    #pragma unroll
                    for (int s4 = 0; 4 * s4 < t; s4++) {
                        float4 abq = ld4(abr + 4 * s4);
                        int s = 4 * s4;
                        if (s     < t) a0 += abq.x * uu[s];
                        if (s + 1 < t) a1 += abq.y * uu[s + 1];
                        if (s + 2 < t) a2 += abq.z * uu[s + 2];
                        if (s + 3 < t) a3 += abq.w * uu[s + 3];
                    }
                    uu[t] = (a0 + a1) + (a2 + a3);
                }
                #pragma unroll
                for (int t = 0; t < DT_; t++) {
                    sm[OFF_U + tw(t, c)] = uu[t];
                    sm[OFF_UT + c * 17 + t] = tf32r(uu[t]);
                }
            }
            BARC();   // u ready

            // ===== y = yp + QKV + qb@u =====
            {
                float4 ypv = ld4(sm + OFF_YP + tx * 68 + 4 * iq);
                float4 qkv = ld4(buf + BQKV + tx * 68 + 4 * iq);
                float4 qbr[4];
                #pragma unroll
                for (int r = 0; r < 4; r++)
                    qbr[r] = ld4(buf + BD32 + (16 + tx) * 36 + 4 * r);
                u64 y01 = pk2(ypv.x + qkv.x, ypv.y + qkv.y);
                u64 y23 = pk2(ypv.z + qkv.z, ypv.w + qkv.w);
                #pragma unroll
                for (int s = 0; s < 16; s++) {
                    float qbs = (s & 2) ? ((s & 1) ? qbr[s >> 2].w : qbr[s >> 2].z)
                                        : ((s & 1) ? qbr[s >> 2].y : qbr[s >> 2].x);
                    ulonglong2 U2 = ldp(sm + OFF_U + tg(s, iq));
                    u64 q2 = pk2(qbs, qbs);
                    fma2(y01, q2, U2.x);
                    fma2(y23, q2, U2.y);
                }
                float o0, o1, o2, o3;
                un2(y01, o0, o1); un2(y23, o2, o3);
                size_t yb = (((size_t)b * T_ + ch * DT_ + tx) * H_ + h) * C_ + 4 * iq;
                __stcs(reinterpret_cast<float4*>(gy + yb), make_float4(o0, o1, o2, o3));
            }

            // ===== ACCU via mma + fused state update: S = (S + av + u^T bwi) * fw =====
            {
                const int m0 = 16 * (w >> 1);
                const int nbase = 32 * (w & 1);
                float4 Cv[4] = {{0,0,0,0}, {0,0,0,0}, {0,0,0,0}, {0,0,0,0}};
                #pragma unroll
                for (int k = 0; k < 2; k++) {
                    const int ca = 8 * k + tq;
                    uint32_t a0 = fu(sm[OFF_UT + (m0 + gid) * 17 + ca]);
                    uint32_t a1 = fu(sm[OFF_UT + (m0 + gid + 8) * 17 + ca]);
                    uint32_t a2 = fu(sm[OFF_UT + (m0 + gid) * 17 + ca + 4]);
                    uint32_t a3 = fu(sm[OFF_UT + (m0 + gid + 8) * 17 + ca + 4]);
                    #pragma unroll
                    for (int j = 0; j < 4; j++) {
                        const int n = nbase + 8 * j;
                        uint32_t b0 = fu(buf[BBWT + (n + gid) * 17 + ca]);
                        uint32_t b1 = fu(buf[BBWT + (n + gid) * 17 + ca + 4]);
                        mma8(Cv[j], a0, a1, a2, a3, b0, b1);
                    }
                }
                #pragma unroll
                for (int j = 0; j < 4; j++) {
                    const int n = nbase + 8 * j;
                    const int c0 = n + 2 * tq;
                    float2 fw2 = *reinterpret_cast<const float2*>(buf + BFW + c0);
                    float* s0p = sm + OFF_S + (m0 + gid) * 68 + c0;
                    float* s1p = sm + OFF_S + (m0 + gid + 8) * 68 + c0;
                    float2 av0 = *reinterpret_cast<const float2*>(av + (m0 + gid) * 68 + c0);
                    float2 av1 = *reinterpret_cast<const float2*>(av + (m0 + gid + 8) * 68 + c0);
                    float2 S0 = *reinterpret_cast<const float2*>(s0p);
                    float2 S1 = *reinterpret_cast<const float2*>(s1p);
                    S0.x = (S0.x + av0.x + Cv[j].x) * fw2.x;
                    S0.y = (S0.y + av0.y + Cv[j].y) * fw2.y;
                    S1.x = (S1.x + av1.x + Cv[j].z) * fw2.x;
                    S1.y = (S1.y + av1.y + Cv[j].w) * fw2.y;
                    *reinterpret_cast<float2*>(s0p) = S0;
                    *reinterpret_cast<float2*>(s1p) = S1;
                }
            }
        }
        __syncthreads();   // buffer handoff + S visibility
    }
}

extern "C" void kernel_launch(void* const* d_in, const int* in_sizes, int n_in,
                              void* d_out, int out_size)
{
    const float* w  = (const float*)d_in[0];
    const float* q  = (const float*)d_in[1];
    const float* k  = (const float*)d_in[2];
    const float* v  = (const float*)d_in[3];
    const float* a  = (const float*)d_in[4];
    const float* b  = (const float*)d_in[5];
    const float* s0 = (const float*)d_in[6];
    float* y = (float*)d_out;

    cudaFuncSetAttribute(rwkv7_kernel, cudaFuncAttributeMaxDynamicSharedMemorySize, SMEM_BYTES);
    rwkv7_kernel<<<B_ * H_, THREADS, SMEM_BYTES>>>(w, q, k, v, a, b, s0, y);
}